// round 14
// baseline (speedup 1.0000x reference)
#include <cuda_runtime.h>
#include <cuda_fp16.h>
#include <mma.h>
#include <cstdint>
#include <math.h>

using namespace nvcuda;

#define B_    32
#define C1    1024
#define N1    512
#define N2    256
#define HW    1024
#define NPIX  (B_*HW)
#define IMG   512
#define RS    384
#define NREG  3

// ---------------- static device scratch ----------------
__device__ __align__(16) __half g_a1h[(size_t)NPIX * C1];
__device__ __align__(16) __half g_a1l[(size_t)NPIX * C1];
__device__ __align__(16) __half g_h1h[(size_t)NPIX * N1];
__device__ __align__(16) __half g_h1l[(size_t)NPIX * N1];
__device__ __align__(16) __half g_w1h[N1 * C1];
__device__ __align__(16) __half g_w1l[N1 * C1];
__device__ __align__(16) __half g_w2h[N2 * N1];
__device__ __align__(16) __half g_w2l[N2 * N1];
__device__ float g_part[2][NPIX];
__device__ float g_att[NPIX];
__device__ int   g_xy[B_ * NREG * 2];

// ---------------- PTX helpers ----------------
__device__ __forceinline__ uint32_t smem_u32(const void* p) {
    uint32_t a;
    asm("{ .reg .u64 t; cvta.to.shared.u64 t, %1; cvt.u32.u64 %0, t; }" : "=r"(a) : "l"(p));
    return a;
}
__device__ __forceinline__ void cp16(uint32_t dst, const void* src) {
    asm volatile("cp.async.cg.shared.global [%0], [%1], 16;" :: "r"(dst), "l"(src));
}
__device__ __forceinline__ void cp_commit() { asm volatile("cp.async.commit_group;" ::: "memory"); }
template<int N> __device__ __forceinline__ void cp_wait() { asm volatile("cp.async.wait_group %0;" :: "n"(N) : "memory"); }

// ---------------- prep: features transpose + fp16 split ----------------
__global__ void conv_feat(const float* __restrict__ f) {
    __shared__ float tile[32][33];
    int b = blockIdx.z, k0 = blockIdx.x * 32, hw0 = blockIdx.y * 32;
    int tx = threadIdx.x & 31, ty = threadIdx.x >> 5;   // 32 x 8
    const float* src = f + ((size_t)b << 20) + (size_t)k0 * 1024 + hw0;
#pragma unroll
    for (int r = 0; r < 4; r++)
        tile[ty + r * 8][tx] = src[(size_t)(ty + r * 8) * 1024 + tx];
    __syncthreads();
#pragma unroll
    for (int r = 0; r < 4; r++) {
        int hw = ty + r * 8;
        float v = tile[tx][hw];
        size_t o = (((size_t)b << 10) + hw0 + hw) * 1024 + k0 + tx;
        __half h = __float2half_rn(v);
        g_a1h[o] = h;
        g_a1l[o] = __float2half_rn(v - __half2float(h));
    }
}

__global__ void conv_w(const float* __restrict__ w, __half* __restrict__ oh,
                       __half* __restrict__ ol, int n) {
    int i = blockIdx.x * 256 + threadIdx.x;
    if (i < n) {
        float v = w[i];
        __half h = __float2half_rn(v);
        oh[i] = h;
        ol[i] = __float2half_rn(v - __half2float(h));
    }
}

// ---------------- fused 3-term wmma GEMM, mixed-precision accumulation ----------------
// CTA tile 128x128, 256 threads (8 warps 4x2, warp tile 32x64), BK=32, 3 stages.
// Packed tiles: 128 rows x 72 halves, cols [0:32)=hi, [32:64)=lo, [64:72)=pad.
// Main term Ah*Bh -> fp32 acc; corrections Al*Bh + Ah*Bl -> shared fp16 acc (2x rate).
#define LDH     72
#define TILE_B  (128*LDH*2)         // 18432
#define STG_B   (2*TILE_B)          // 36864 per stage (A2 + B2)
#define LDS_    132
#define LDS16   136
#define STG16_OFF (128*LDS_*4)      // 67584, fp16 staging after fp32 staging
#define SMEM_DYN (3*STG_B)          // 110592 (>= 67584 + 128*136*2 = 102400)

template<int K, bool FINAL>
__global__ __launch_bounds__(256, 2)
void gemm_hmma(const __half* __restrict__ a_h, const __half* __restrict__ a_l,
               const __half* __restrict__ b_h, const __half* __restrict__ b_l,
               const float* __restrict__ bias, int Nout,
               __half* __restrict__ outh, __half* __restrict__ outl,
               const float* __restrict__ w3, float* __restrict__ part)
{
    extern __shared__ char sm[];
    __shared__ float s_w3[128];
    const int t = threadIdx.x;
    const int warp = t >> 5;
    const int lane = t & 31;
    const int warpM = warp >> 1, warpN = warp & 1;   // 4 x 2 warps, each 32 x 64
    const int mBase = blockIdx.y * 128, nBase = blockIdx.x * 128;

    constexpr int KC = K >> 5;       // BK = 32

    const uint32_t sbase = smem_u32(sm);

    if (FINAL && t < 128) s_w3[t] = w3[nBase + t];

    const __half* srcA[4];
    const __half* srcB[4];
    int gOffA[4], gOffB[4];
    uint32_t dOff[4];
#pragma unroll
    for (int u = 0; u < 4; u++) {
        int i = u * 256 + t;             // 0..1023
        int row = i >> 3, sub = i & 7;   // sub 0-3 hi, 4-7 lo
        int col = (sub & 3) * 8;
        srcA[u] = (sub < 4) ? a_h : a_l;
        srcB[u] = (sub < 4) ? b_h : b_l;
        gOffA[u] = (mBase + row) * K + col;
        gOffB[u] = (nBase + row) * K + col;
        dOff[u] = (uint32_t)row * (LDH * 2) + (uint32_t)sub * 16;
    }

    wmma::fragment<wmma::accumulator, 16, 16, 16, float>  acc32[2][4];
    wmma::fragment<wmma::accumulator, 16, 16, 16, __half> acc16[2][4];
#pragma unroll
    for (int i = 0; i < 2; i++)
#pragma unroll
        for (int j = 0; j < 4; j++) {
            wmma::fill_fragment(acc32[i][j], 0.f);
            wmma::fill_fragment(acc16[i][j], __float2half(0.f));
        }

    auto issue = [&](int kk) {
        const int kc = kk << 5;
        const uint32_t sb = sbase + (kk % 3) * STG_B;
#pragma unroll
        for (int u = 0; u < 4; u++) {
            cp16(sb +          dOff[u], srcA[u] + gOffA[u] + kc);
            cp16(sb + TILE_B + dOff[u], srcB[u] + gOffB[u] + kc);
        }
    };

    issue(0); cp_commit();
    issue(1); cp_commit();

    for (int kk = 0; kk < KC; kk++) {
        const int s = kk % 3;
        cp_wait<1>();
        __syncthreads();
        const __half* A2 = (const __half*)(sm + s * STG_B)          + (warpM * 32) * LDH;
        const __half* B2 = (const __half*)(sm + s * STG_B + TILE_B) + (warpN * 64) * LDH;

        wmma::fragment<wmma::matrix_a, 16, 16, 16, __half, wmma::row_major> af[2];
        wmma::fragment<wmma::matrix_b, 16, 16, 16, __half, wmma::col_major> bf;
#pragma unroll
        for (int k16 = 0; k16 < 2; k16++) {
            // pass 1: main term hi(A)*hi(B) -> fp32 acc
            wmma::load_matrix_sync(af[0], A2 + k16 * 16, LDH);
            wmma::load_matrix_sync(af[1], A2 + 16 * LDH + k16 * 16, LDH);
#pragma unroll
            for (int j = 0; j < 4; j++) {
                wmma::load_matrix_sync(bf, B2 + j * 16 * LDH + k16 * 16, LDH);
                wmma::mma_sync(acc32[0][j], af[0], bf, acc32[0][j]);
                wmma::mma_sync(acc32[1][j], af[1], bf, acc32[1][j]);
            }
            // pass 2: correction lo(A)*hi(B) -> fp16 acc
            wmma::load_matrix_sync(af[0], A2 + 32 + k16 * 16, LDH);
            wmma::load_matrix_sync(af[1], A2 + 16 * LDH + 32 + k16 * 16, LDH);
#pragma unroll
            for (int j = 0; j < 4; j++) {
                wmma::load_matrix_sync(bf, B2 + j * 16 * LDH + k16 * 16, LDH);
                wmma::mma_sync(acc16[0][j], af[0], bf, acc16[0][j]);
                wmma::mma_sync(acc16[1][j], af[1], bf, acc16[1][j]);
            }
            // pass 3: correction hi(A)*lo(B) -> fp16 acc
            wmma::load_matrix_sync(af[0], A2 + k16 * 16, LDH);
            wmma::load_matrix_sync(af[1], A2 + 16 * LDH + k16 * 16, LDH);
#pragma unroll
            for (int j = 0; j < 4; j++) {
                wmma::load_matrix_sync(bf, B2 + j * 16 * LDH + 32 + k16 * 16, LDH);
                wmma::mma_sync(acc16[0][j], af[0], bf, acc16[0][j]);
                wmma::mma_sync(acc16[1][j], af[1], bf, acc16[1][j]);
            }
        }
        if (kk + 2 < KC) issue(kk + 2);
        cp_commit();
    }

    cp_wait<0>();
    __syncthreads();
    float*  stg   = (float*)sm;
    __half* stg16 = (__half*)(sm + STG16_OFF);
#pragma unroll
    for (int i = 0; i < 2; i++)
#pragma unroll
        for (int j = 0; j < 4; j++) {
            wmma::store_matrix_sync(stg + (warpM * 32 + i * 16) * LDS_ + warpN * 64 + j * 16,
                                    acc32[i][j], LDS_, wmma::mem_row_major);
            wmma::store_matrix_sync(stg16 + (warpM * 32 + i * 16) * LDS16 + warpN * 64 + j * 16,
                                    acc16[i][j], LDS16, wmma::mem_row_major);
        }
    __syncthreads();

    if (!FINAL) {
#pragma unroll
        for (int it = 0; it < 32; it++) {
            int i = it * 256 + t;            // half2 index, 8192 total
            int lr = i >> 6, lc = (i & 63) << 1;
            float v0 = stg[lr * LDS_ + lc]     + __half2float(stg16[lr * LDS16 + lc])
                     + bias[nBase + lc];
            float v1 = stg[lr * LDS_ + lc + 1] + __half2float(stg16[lr * LDS16 + lc + 1])
                     + bias[nBase + lc + 1];
            v0 = fmaxf(v0, 0.f);
            v1 = fmaxf(v1, 0.f);
            __half h0 = __float2half_rn(v0), h1 = __float2half_rn(v1);
            __half l0 = __float2half_rn(v0 - __half2float(h0));
            __half l1 = __float2half_rn(v1 - __half2float(h1));
            size_t o = (size_t)(mBase + lr) * Nout + nBase + lc;
            *(__half2*)(outh + o) = __halves2half2(h0, h1);
            *(__half2*)(outl + o) = __halves2half2(l0, l1);
        }
    } else {
        // fused layer-3 partial dot: each warp handles 16 rows of 128 cols
#pragma unroll
        for (int rr = 0; rr < 16; rr++) {
            int row = warp * 16 + rr;
            float s = 0.f;
#pragma unroll
            for (int q = 0; q < 4; q++) {
                int c = q * 32 + lane;
                float v = stg[row * LDS_ + c] + __half2float(stg16[row * LDS16 + c])
                        + bias[nBase + c];
                s = fmaf(fmaxf(v, 0.f), s_w3[c], s);
            }
#pragma unroll
            for (int off = 16; off; off >>= 1)
                s += __shfl_down_sync(0xffffffffu, s, off);
            if (lane == 0)
                part[(size_t)blockIdx.x * NPIX + mBase + row] = s;
        }
    }
}

// ---------------- finalize att: sum partials + sigmoid + CAM ----------------
__global__ void finalize_att(const float* __restrict__ b3, const float* __restrict__ cam,
                             float* __restrict__ att_out)
{
    int p = blockIdx.x * 256 + threadIdx.x;
    float s = g_part[0][p] + g_part[1][p] + b3[0];
    float v = 1.f / (1.f + expf(-s));
    float a = (v + cam[p]) * 0.5f;
    g_att[p] = a;
    att_out[p] = a;
}

// ---------------- peak picking ----------------
__global__ void peaks_kernel(float* __restrict__ coords_out)
{
    __shared__ float smv[1024];
    __shared__ float rv[8];
    __shared__ int   ri[8];
    __shared__ int   s_fy, s_fx;

    const int b = blockIdx.x;
    const int t = threadIdx.x;

    for (int i = t; i < 1024; i += 256) smv[i] = g_att[b * 1024 + i];
    __syncthreads();

    for (int k = 0; k < NREG; k++) {
        float best = -1.f;
        int bi = 1 << 30;
        for (int i = t; i < 1024; i += 256) {
            float v = smv[i];
            if (v > best) { best = v; bi = i; }
        }
#pragma unroll
        for (int off = 16; off; off >>= 1) {
            float ov = __shfl_down_sync(0xffffffffu, best, off);
            int   oi = __shfl_down_sync(0xffffffffu, bi, off);
            if (ov > best || (ov == best && oi < bi)) { best = ov; bi = oi; }
        }
        if ((t & 31) == 0) { rv[t >> 5] = best; ri[t >> 5] = bi; }
        __syncthreads();
        if (t == 0) {
            for (int w = 1; w < 8; w++)
                if (rv[w] > best || (rv[w] == best && ri[w] < bi)) { best = rv[w]; bi = ri[w]; }
            int fy = bi >> 5, fx = bi & 31;
            if (!(best > 0.f)) { fy = 16; fx = 16; }
            int y1 = min(max(fy * 16 - (RS / 2), 0), IMG - RS);
            int x1 = min(max(fx * 16 - (RS / 2), 0), IMG - RS);
            int r = b * NREG + k;
            g_xy[r * 2 + 0] = y1;
            g_xy[r * 2 + 1] = x1;
            float* cp = coords_out + r * 4;
            cp[0] = (float)x1;
            cp[1] = (float)y1;
            cp[2] = (float)(x1 + RS);
            cp[3] = (float)(y1 + RS);
            s_fy = fy; s_fx = fx;
        }
        __syncthreads();
        int fy = s_fy, fx = s_fx;
        for (int i = t; i < 1024; i += 256) {
            int y = i >> 5, x = i & 31;
            if (abs(y - fy) <= 5 && abs(x - fx) <= 5) smv[i] = 0.f;
        }
        __syncthreads();
    }
}

// ---------------- region crops ----------------
__global__ void crop_kernel(const float* __restrict__ orig, float* __restrict__ out)
{
    const int r = blockIdx.y;
    const int b = r / NREG;
    const int y1 = g_xy[r * 2 + 0];
    const int x1 = g_xy[r * 2 + 1];

    int idx = blockIdx.x * blockDim.x + threadIdx.x;
    int col4 = idx % 96;
    int tmp  = idx / 96;
    int rrow = tmp % RS;
    int c    = tmp / RS;

    const float* src = orig + (((size_t)(b * 3 + c) * IMG) + (y1 + rrow)) * IMG + x1;
    float4 v = *((const float4*)src + col4);
    float4* dst = (float4*)(out + (size_t)r * (3 * RS * RS)) + idx;
    *dst = v;
}

// ---------------- launch ----------------
extern "C" void kernel_launch(void* const* d_in, const int* in_sizes, int n_in,
                              void* d_out, int out_size)
{
    const float* features = (const float*)d_in[0];
    const float* cam      = (const float*)d_in[1];
    const float* original = (const float*)d_in[2];
    const float* w1 = (const float*)d_in[3];
    const float* b1 = (const float*)d_in[4];
    const float* w2 = (const float*)d_in[5];
    const float* b2 = (const float*)d_in[6];
    const float* w3 = (const float*)d_in[7];
    const float* b3 = (const float*)d_in[8];

    float* out = (float*)d_out;
    const size_t regions_elems = (size_t)B_ * NREG * 3 * RS * RS;
    float* coords_out = out + regions_elems;
    float* att_out    = coords_out + (size_t)B_ * NREG * 4;

    __half *a1h, *a1l, *h1h, *h1l, *w1h, *w1l, *w2h, *w2l;
    float *part;
    cudaGetSymbolAddress((void**)&a1h, g_a1h);
    cudaGetSymbolAddress((void**)&a1l, g_a1l);
    cudaGetSymbolAddress((void**)&h1h, g_h1h);
    cudaGetSymbolAddress((void**)&h1l, g_h1l);
    cudaGetSymbolAddress((void**)&w1h, g_w1h);
    cudaGetSymbolAddress((void**)&w1l, g_w1l);
    cudaGetSymbolAddress((void**)&w2h, g_w2h);
    cudaGetSymbolAddress((void**)&w2l, g_w2l);
    cudaGetSymbolAddress((void**)&part, g_part);

    cudaFuncSetAttribute(gemm_hmma<C1, false>, cudaFuncAttributeMaxDynamicSharedMemorySize, SMEM_DYN);
    cudaFuncSetAttribute(gemm_hmma<N1, true>,  cudaFuncAttributeMaxDynamicSharedMemorySize, SMEM_DYN);

    conv_feat<<<dim3(32, 32, 32), 256>>>(features);
    conv_w<<<(N1 * C1 + 255) / 256, 256>>>(w1, w1h, w1l, N1 * C1);
    conv_w<<<(N2 * N1 + 255) / 256, 256>>>(w2, w2h, w2l, N2 * N1);

    // GEMM1: relu(features x w1^T + b1) -> h1 (fp16 split out)
    gemm_hmma<C1, false><<<dim3(N1 / 128, NPIX / 128), 256, SMEM_DYN>>>(
        a1h, a1l, w1h, w1l, b1, N1, h1h, h1l, nullptr, nullptr);
    // GEMM2 + fused layer3 partial dot
    gemm_hmma<N1, true><<<dim3(N2 / 128, NPIX / 128), 256, SMEM_DYN>>>(
        h1h, h1l, w2h, w2l, b2, N2, nullptr, nullptr, w3, part);

    finalize_att<<<NPIX / 256, 256>>>(b3, cam, att_out);
    peaks_kernel<<<B_, 256>>>(coords_out);
    crop_kernel<<<dim3(432, B_ * NREG), 256>>>(original, out);
}

// round 15
// speedup vs baseline: 1.1043x; 1.1043x over previous
#include <cuda_runtime.h>
#include <cuda_fp16.h>
#include <mma.h>
#include <cstdint>
#include <math.h>

using namespace nvcuda;

#define B_    32
#define C1    1024
#define N1    512
#define N2    256
#define HW    1024
#define NPIX  (B_*HW)
#define IMG   512
#define RS    384
#define NREG  3

// ---------------- static device scratch ----------------
__device__ __align__(16) __half g_a1h[(size_t)NPIX * C1];
__device__ __align__(16) __half g_a1l[(size_t)NPIX * C1];
__device__ __align__(16) __half g_h1h[(size_t)NPIX * N1];
__device__ __align__(16) __half g_h1l[(size_t)NPIX * N1];
__device__ __align__(16) __half g_w1h[N1 * C1];
__device__ __align__(16) __half g_w1l[N1 * C1];
__device__ __align__(16) __half g_w2h[N2 * N1];
__device__ __align__(16) __half g_w2l[N2 * N1];
__device__ float g_part[2][NPIX];
__device__ float g_att[NPIX];
__device__ int   g_xy[B_ * NREG * 2];

// ---------------- PTX helpers ----------------
__device__ __forceinline__ uint32_t smem_u32(const void* p) {
    uint32_t a;
    asm("{ .reg .u64 t; cvta.to.shared.u64 t, %1; cvt.u32.u64 %0, t; }" : "=r"(a) : "l"(p));
    return a;
}
__device__ __forceinline__ void cp16(uint32_t dst, const void* src) {
    asm volatile("cp.async.cg.shared.global [%0], [%1], 16;" :: "r"(dst), "l"(src));
}
__device__ __forceinline__ void cp_commit() { asm volatile("cp.async.commit_group;" ::: "memory"); }
template<int N> __device__ __forceinline__ void cp_wait() { asm volatile("cp.async.wait_group %0;" :: "n"(N) : "memory"); }

// ---------------- prep: features transpose + fp16 split (vectorized writes) ----------
// block handles one (b, k0:64, hw0:32) tile. Reads coalesced along hw,
// writes __half2 (two k per thread) -> 128B per warp transaction.
__global__ void conv_feat(const float* __restrict__ f) {
    __shared__ float tile[64][33];
    int b = blockIdx.z, k0 = blockIdx.x * 64, hw0 = blockIdx.y * 32;
    int tx = threadIdx.x & 31, ty = threadIdx.x >> 5;   // 32 x 8
    const float* src = f + ((size_t)b << 20) + (size_t)k0 * 1024 + hw0;
#pragma unroll
    for (int r = 0; r < 8; r++)
        tile[ty + r * 8][tx] = src[(size_t)(ty + r * 8) * 1024 + tx];
    __syncthreads();
    // write: tx = k-pair (0..31), each covers k = 2*tx, 2*tx+1; rows = hw
#pragma unroll
    for (int r = 0; r < 4; r++) {
        int hw = ty + r * 8;
        float v0 = tile[tx * 2][hw];
        float v1 = tile[tx * 2 + 1][hw];
        __half h0 = __float2half_rn(v0), h1 = __float2half_rn(v1);
        __half l0 = __float2half_rn(v0 - __half2float(h0));
        __half l1 = __float2half_rn(v1 - __half2float(h1));
        size_t o = (((size_t)b << 10) + hw0 + hw) * 1024 + k0 + tx * 2;
        *(__half2*)(g_a1h + o) = __halves2half2(h0, h1);
        *(__half2*)(g_a1l + o) = __halves2half2(l0, l1);
    }
}

__global__ void conv_w(const float* __restrict__ w, __half* __restrict__ oh,
                       __half* __restrict__ ol, int n) {
    int i = blockIdx.x * 256 + threadIdx.x;
    if (i < n) {
        float v = w[i];
        __half h = __float2half_rn(v);
        oh[i] = h;
        ol[i] = __float2half_rn(v - __half2float(h));
    }
}

// ---------------- fused 3-term wmma GEMM: C = relu(A*W^T + b) ----------------
// CTA tile 128x128, 256 threads (8 warps 4x2, warp tile 32x64), BK=32, 3 stages.
// Packed tiles: 128 rows x 72 halves, cols [0:32)=hi, [32:64)=lo, [64:72)=pad.
#define LDH     72
#define TILE_B  (128*LDH*2)         // 18432
#define STG_B   (2*TILE_B)          // 36864 per stage (A2 + B2)
#define LDS_    132
#define SMEM_DYN (3*STG_B)          // 110592

template<int K, bool FINAL>
__global__ __launch_bounds__(256, 2)
void gemm_hmma(const __half* __restrict__ a_h, const __half* __restrict__ a_l,
               const __half* __restrict__ b_h, const __half* __restrict__ b_l,
               const float* __restrict__ bias, int Nout,
               __half* __restrict__ outh, __half* __restrict__ outl,
               const float* __restrict__ w3, float* __restrict__ part)
{
    extern __shared__ char sm[];
    __shared__ float s_w3[128];
    const int t = threadIdx.x;
    const int warp = t >> 5;
    const int lane = t & 31;
    const int warpM = warp >> 1, warpN = warp & 1;   // 4 x 2 warps, each 32 x 64
    const int mBase = blockIdx.y * 128, nBase = blockIdx.x * 128;

    constexpr int KC = K >> 5;       // BK = 32

    const uint32_t sbase = smem_u32(sm);

    if (FINAL && t < 128) s_w3[t] = w3[nBase + t];

    const __half* srcA[4];
    const __half* srcB[4];
    int gOffA[4], gOffB[4];
    uint32_t dOff[4];
#pragma unroll
    for (int u = 0; u < 4; u++) {
        int i = u * 256 + t;             // 0..1023
        int row = i >> 3, sub = i & 7;   // sub 0-3 hi, 4-7 lo
        int col = (sub & 3) * 8;
        srcA[u] = (sub < 4) ? a_h : a_l;
        srcB[u] = (sub < 4) ? b_h : b_l;
        gOffA[u] = (mBase + row) * K + col;
        gOffB[u] = (nBase + row) * K + col;
        dOff[u] = (uint32_t)row * (LDH * 2) + (uint32_t)sub * 16;
    }

    wmma::fragment<wmma::accumulator, 16, 16, 16, float> acc[2][4];
#pragma unroll
    for (int i = 0; i < 2; i++)
#pragma unroll
        for (int j = 0; j < 4; j++)
            wmma::fill_fragment(acc[i][j], 0.f);

    auto issue = [&](int kk, int s) {
        const int kc = kk << 5;
        const uint32_t sb = sbase + s * STG_B;
#pragma unroll
        for (int u = 0; u < 4; u++) {
            cp16(sb +          dOff[u], srcA[u] + gOffA[u] + kc);
            cp16(sb + TILE_B + dOff[u], srcB[u] + gOffB[u] + kc);
        }
    };

    issue(0, 0); cp_commit();
    issue(1, 1); cp_commit();

#pragma unroll 3
    for (int kk = 0; kk < KC; kk++) {
        const int s = kk % 3;
        cp_wait<1>();
        __syncthreads();
        const __half* A2 = (const __half*)(sm + s * STG_B)          + (warpM * 32) * LDH;
        const __half* B2 = (const __half*)(sm + s * STG_B + TILE_B) + (warpN * 64) * LDH;

        wmma::fragment<wmma::matrix_a, 16, 16, 16, __half, wmma::row_major> afh[2], afl[2];
        wmma::fragment<wmma::matrix_b, 16, 16, 16, __half, wmma::col_major> bf[2];
#pragma unroll
        for (int k16 = 0; k16 < 2; k16++) {
            wmma::load_matrix_sync(afh[0], A2 + k16 * 16, LDH);
            wmma::load_matrix_sync(afh[1], A2 + 16 * LDH + k16 * 16, LDH);
            wmma::load_matrix_sync(afl[0], A2 + 32 + k16 * 16, LDH);
            wmma::load_matrix_sync(afl[1], A2 + 16 * LDH + 32 + k16 * 16, LDH);

            // pass 1: hi(A) * hi(B)
            wmma::load_matrix_sync(bf[0], B2 + k16 * 16, LDH);
#pragma unroll
            for (int j = 0; j < 4; j++) {
                if (j < 3)
                    wmma::load_matrix_sync(bf[(j + 1) & 1], B2 + (j + 1) * 16 * LDH + k16 * 16, LDH);
                wmma::mma_sync(acc[0][j], afh[0], bf[j & 1], acc[0][j]);
                wmma::mma_sync(acc[1][j], afh[1], bf[j & 1], acc[1][j]);
            }
            // pass 2: lo(A) * hi(B)
            wmma::load_matrix_sync(bf[0], B2 + k16 * 16, LDH);
#pragma unroll
            for (int j = 0; j < 4; j++) {
                if (j < 3)
                    wmma::load_matrix_sync(bf[(j + 1) & 1], B2 + (j + 1) * 16 * LDH + k16 * 16, LDH);
                wmma::mma_sync(acc[0][j], afl[0], bf[j & 1], acc[0][j]);
                wmma::mma_sync(acc[1][j], afl[1], bf[j & 1], acc[1][j]);
            }
            // pass 3: hi(A) * lo(B)
            wmma::load_matrix_sync(bf[0], B2 + 32 + k16 * 16, LDH);
#pragma unroll
            for (int j = 0; j < 4; j++) {
                if (j < 3)
                    wmma::load_matrix_sync(bf[(j + 1) & 1], B2 + (j + 1) * 16 * LDH + 32 + k16 * 16, LDH);
                wmma::mma_sync(acc[0][j], afh[0], bf[j & 1], acc[0][j]);
                wmma::mma_sync(acc[1][j], afh[1], bf[j & 1], acc[1][j]);
            }
        }
        if (kk + 2 < KC) issue(kk + 2, (kk + 2) % 3);
        cp_commit();
    }

    cp_wait<0>();
    __syncthreads();
    float* stg = (float*)sm;
#pragma unroll
    for (int i = 0; i < 2; i++)
#pragma unroll
        for (int j = 0; j < 4; j++)
            wmma::store_matrix_sync(stg + (warpM * 32 + i * 16) * LDS_ + warpN * 64 + j * 16,
                                    acc[i][j], LDS_, wmma::mem_row_major);
    __syncthreads();

    if (!FINAL) {
#pragma unroll
        for (int it = 0; it < 32; it++) {
            int i = it * 256 + t;            // half2 index, 8192 total
            int lr = i >> 6, lc = (i & 63) << 1;
            float v0 = fmaxf(stg[lr * LDS_ + lc]     + bias[nBase + lc],     0.f);
            float v1 = fmaxf(stg[lr * LDS_ + lc + 1] + bias[nBase + lc + 1], 0.f);
            __half h0 = __float2half_rn(v0), h1 = __float2half_rn(v1);
            __half l0 = __float2half_rn(v0 - __half2float(h0));
            __half l1 = __float2half_rn(v1 - __half2float(h1));
            size_t o = (size_t)(mBase + lr) * Nout + nBase + lc;
            *(__half2*)(outh + o) = __halves2half2(h0, h1);
            *(__half2*)(outl + o) = __halves2half2(l0, l1);
        }
    } else {
        // fused layer-3 partial dot: each warp handles 16 rows of 128 cols
#pragma unroll
        for (int rr = 0; rr < 16; rr++) {
            int row = warp * 16 + rr;
            float s = 0.f;
#pragma unroll
            for (int q = 0; q < 4; q++) {
                int c = q * 32 + lane;
                float v = fmaxf(stg[row * LDS_ + c] + bias[nBase + c], 0.f);
                s = fmaf(v, s_w3[c], s);
            }
#pragma unroll
            for (int off = 16; off; off >>= 1)
                s += __shfl_down_sync(0xffffffffu, s, off);
            if (lane == 0)
                part[(size_t)blockIdx.x * NPIX + mBase + row] = s;
        }
    }
}

// ---------------- finalize att: sum partials + sigmoid + CAM ----------------
__global__ void finalize_att(const float* __restrict__ b3, const float* __restrict__ cam,
                             float* __restrict__ att_out)
{
    int p = blockIdx.x * 256 + threadIdx.x;
    float s = g_part[0][p] + g_part[1][p] + b3[0];
    float v = 1.f / (1.f + expf(-s));
    float a = (v + cam[p]) * 0.5f;
    g_att[p] = a;
    att_out[p] = a;
}

// ---------------- peak picking ----------------
__global__ void peaks_kernel(float* __restrict__ coords_out)
{
    __shared__ float smv[1024];
    __shared__ float rv[8];
    __shared__ int   ri[8];
    __shared__ int   s_fy, s_fx;

    const int b = blockIdx.x;
    const int t = threadIdx.x;

    for (int i = t; i < 1024; i += 256) smv[i] = g_att[b * 1024 + i];
    __syncthreads();

    for (int k = 0; k < NREG; k++) {
        float best = -1.f;
        int bi = 1 << 30;
        for (int i = t; i < 1024; i += 256) {
            float v = smv[i];
            if (v > best) { best = v; bi = i; }
        }
#pragma unroll
        for (int off = 16; off; off >>= 1) {
            float ov = __shfl_down_sync(0xffffffffu, best, off);
            int   oi = __shfl_down_sync(0xffffffffu, bi, off);
            if (ov > best || (ov == best && oi < bi)) { best = ov; bi = oi; }
        }
        if ((t & 31) == 0) { rv[t >> 5] = best; ri[t >> 5] = bi; }
        __syncthreads();
        if (t == 0) {
            for (int w = 1; w < 8; w++)
                if (rv[w] > best || (rv[w] == best && ri[w] < bi)) { best = rv[w]; bi = ri[w]; }
            int fy = bi >> 5, fx = bi & 31;
            if (!(best > 0.f)) { fy = 16; fx = 16; }
            int y1 = min(max(fy * 16 - (RS / 2), 0), IMG - RS);
            int x1 = min(max(fx * 16 - (RS / 2), 0), IMG - RS);
            int r = b * NREG + k;
            g_xy[r * 2 + 0] = y1;
            g_xy[r * 2 + 1] = x1;
            float* cp = coords_out + r * 4;
            cp[0] = (float)x1;
            cp[1] = (float)y1;
            cp[2] = (float)(x1 + RS);
            cp[3] = (float)(y1 + RS);
            s_fy = fy; s_fx = fx;
        }
        __syncthreads();
        int fy = s_fy, fx = s_fx;
        for (int i = t; i < 1024; i += 256) {
            int y = i >> 5, x = i & 31;
            if (abs(y - fy) <= 5 && abs(x - fx) <= 5) smv[i] = 0.f;
        }
        __syncthreads();
    }
}

// ---------------- region crops ----------------
__global__ void crop_kernel(const float* __restrict__ orig, float* __restrict__ out)
{
    const int r = blockIdx.y;
    const int b = r / NREG;
    const int y1 = g_xy[r * 2 + 0];
    const int x1 = g_xy[r * 2 + 1];

    int idx = blockIdx.x * blockDim.x + threadIdx.x;
    int col4 = idx % 96;
    int tmp  = idx / 96;
    int rrow = tmp % RS;
    int c    = tmp / RS;

    const float* src = orig + (((size_t)(b * 3 + c) * IMG) + (y1 + rrow)) * IMG + x1;
    float4 v = *((const float4*)src + col4);
    float4* dst = (float4*)(out + (size_t)r * (3 * RS * RS)) + idx;
    *dst = v;
}

// ---------------- launch ----------------
extern "C" void kernel_launch(void* const* d_in, const int* in_sizes, int n_in,
                              void* d_out, int out_size)
{
    const float* features = (const float*)d_in[0];
    const float* cam      = (const float*)d_in[1];
    const float* original = (const float*)d_in[2];
    const float* w1 = (const float*)d_in[3];
    const float* b1 = (const float*)d_in[4];
    const float* w2 = (const float*)d_in[5];
    const float* b2 = (const float*)d_in[6];
    const float* w3 = (const float*)d_in[7];
    const float* b3 = (const float*)d_in[8];

    float* out = (float*)d_out;
    const size_t regions_elems = (size_t)B_ * NREG * 3 * RS * RS;
    float* coords_out = out + regions_elems;
    float* att_out    = coords_out + (size_t)B_ * NREG * 4;

    __half *a1h, *a1l, *h1h, *h1l, *w1h, *w1l, *w2h, *w2l;
    float *part;
    cudaGetSymbolAddress((void**)&a1h, g_a1h);
    cudaGetSymbolAddress((void**)&a1l, g_a1l);
    cudaGetSymbolAddress((void**)&h1h, g_h1h);
    cudaGetSymbolAddress((void**)&h1l, g_h1l);
    cudaGetSymbolAddress((void**)&w1h, g_w1h);
    cudaGetSymbolAddress((void**)&w1l, g_w1l);
    cudaGetSymbolAddress((void**)&w2h, g_w2h);
    cudaGetSymbolAddress((void**)&w2l, g_w2l);
    cudaGetSymbolAddress((void**)&part, g_part);

    cudaFuncSetAttribute(gemm_hmma<C1, false>, cudaFuncAttributeMaxDynamicSharedMemorySize, SMEM_DYN);
    cudaFuncSetAttribute(gemm_hmma<N1, true>,  cudaFuncAttributeMaxDynamicSharedMemorySize, SMEM_DYN);

    conv_feat<<<dim3(16, 32, 32), 256>>>(features);
    conv_w<<<(N1 * C1 + 255) / 256, 256>>>(w1, w1h, w1l, N1 * C1);
    conv_w<<<(N2 * N1 + 255) / 256, 256>>>(w2, w2h, w2l, N2 * N1);

    // GEMM1: relu(features x w1^T + b1) -> h1 (fp16 split out)
    gemm_hmma<C1, false><<<dim3(N1 / 128, NPIX / 128), 256, SMEM_DYN>>>(
        a1h, a1l, w1h, w1l, b1, N1, h1h, h1l, nullptr, nullptr);
    // GEMM2 + fused layer3 partial dot
    gemm_hmma<N1, true><<<dim3(N2 / 128, NPIX / 128), 256, SMEM_DYN>>>(
        h1h, h1l, w2h, w2l, b2, N2, nullptr, nullptr, w3, part);

    finalize_att<<<NPIX / 256, 256>>>(b3, cam, att_out);
    peaks_kernel<<<B_, 256>>>(coords_out);
    crop_kernel<<<dim3(432, B_ * NREG), 256>>>(original, out);
}

// round 16
// speedup vs baseline: 1.1444x; 1.0363x over previous
#include <cuda_runtime.h>
#include <cuda_fp16.h>
#include <mma.h>
#include <cstdint>
#include <math.h>

using namespace nvcuda;

#define B_    32
#define C1    1024
#define N1    512
#define N2    256
#define HW    1024
#define NPIX  (B_*HW)
#define IMG   512
#define RS    384
#define NREG  3

// ---------------- static device scratch ----------------
__device__ __align__(16) __half g_a1h[(size_t)NPIX * C1];
__device__ __align__(16) __half g_a1l[(size_t)NPIX * C1];
__device__ __align__(16) __half g_h1h[(size_t)NPIX * N1];
__device__ __align__(16) __half g_h1l[(size_t)NPIX * N1];
__device__ __align__(16) __half g_w1h[N1 * C1];
__device__ __align__(16) __half g_w1l[N1 * C1];
__device__ __align__(16) __half g_w2h[N2 * N1];
__device__ __align__(16) __half g_w2l[N2 * N1];
__device__ float g_part[2][NPIX];
__device__ float g_att[NPIX];
__device__ int   g_xy[B_ * NREG * 2];

// ---------------- PTX helpers ----------------
__device__ __forceinline__ uint32_t smem_u32(const void* p) {
    uint32_t a;
    asm("{ .reg .u64 t; cvta.to.shared.u64 t, %1; cvt.u32.u64 %0, t; }" : "=r"(a) : "l"(p));
    return a;
}
__device__ __forceinline__ void cp16(uint32_t dst, const void* src) {
    asm volatile("cp.async.cg.shared.global [%0], [%1], 16;" :: "r"(dst), "l"(src));
}
__device__ __forceinline__ void cp_commit() { asm volatile("cp.async.commit_group;" ::: "memory"); }
template<int N> __device__ __forceinline__ void cp_wait() { asm volatile("cp.async.wait_group %0;" :: "n"(N) : "memory"); }

// ---------------- prep: features transpose + fp16 split (vectorized writes) ----------
__global__ void conv_feat(const float* __restrict__ f) {
    __shared__ float tile[64][33];
    int b = blockIdx.z, k0 = blockIdx.x * 64, hw0 = blockIdx.y * 32;
    int tx = threadIdx.x & 31, ty = threadIdx.x >> 5;   // 32 x 8
    const float* src = f + ((size_t)b << 20) + (size_t)k0 * 1024 + hw0;
#pragma unroll
    for (int r = 0; r < 8; r++)
        tile[ty + r * 8][tx] = src[(size_t)(ty + r * 8) * 1024 + tx];
    __syncthreads();
#pragma unroll
    for (int r = 0; r < 4; r++) {
        int hw = ty + r * 8;
        float v0 = tile[tx * 2][hw];
        float v1 = tile[tx * 2 + 1][hw];
        __half h0 = __float2half_rn(v0), h1 = __float2half_rn(v1);
        __half l0 = __float2half_rn(v0 - __half2float(h0));
        __half l1 = __float2half_rn(v1 - __half2float(h1));
        size_t o = (((size_t)b << 10) + hw0 + hw) * 1024 + k0 + tx * 2;
        *(__half2*)(g_a1h + o) = __halves2half2(h0, h1);
        *(__half2*)(g_a1l + o) = __halves2half2(l0, l1);
    }
}

__global__ void conv_w(const float* __restrict__ w, __half* __restrict__ oh,
                       __half* __restrict__ ol, int n) {
    int i = blockIdx.x * 256 + threadIdx.x;
    if (i < n) {
        float v = w[i];
        __half h = __float2half_rn(v);
        oh[i] = h;
        ol[i] = __float2half_rn(v - __half2float(h));
    }
}

// ---------------- fused 3-term wmma GEMM: C = relu(A*W^T + b) ----------------
// CTA tile 128x128, 256 threads (8 warps 4x2, warp tile 32x64), BK=32, 3 stages.
// Packed tiles: 128 rows x 72 halves, cols [0:32)=hi, [32:64)=lo, [64:72)=pad.
#define LDH     72
#define TILE_B  (128*LDH*2)         // 18432
#define STG_B   (2*TILE_B)          // 36864 per stage (A2 + B2)
#define LDS_    132
#define SMEM_DYN (3*STG_B)          // 110592

template<int K, bool FINAL>
__global__ __launch_bounds__(256, 2)
void gemm_hmma(const __half* __restrict__ a_h, const __half* __restrict__ a_l,
               const __half* __restrict__ b_h, const __half* __restrict__ b_l,
               const float* __restrict__ bias, int Nout,
               __half* __restrict__ outh, __half* __restrict__ outl,
               const float* __restrict__ w3, float* __restrict__ part)
{
    extern __shared__ char sm[];
    __shared__ float s_w3[128];
    const int t = threadIdx.x;
    const int warp = t >> 5;
    const int lane = t & 31;
    const int warpM = warp >> 1, warpN = warp & 1;   // 4 x 2 warps, each 32 x 64
    const int mBase = blockIdx.y * 128, nBase = blockIdx.x * 128;

    constexpr int KC = K >> 5;       // BK = 32

    const uint32_t sbase = smem_u32(sm);

    if (FINAL && t < 128) s_w3[t] = w3[nBase + t];

    const __half* srcA[4];
    const __half* srcB[4];
    int gOffA[4], gOffB[4];
    uint32_t dOff[4];
#pragma unroll
    for (int u = 0; u < 4; u++) {
        int i = u * 256 + t;             // 0..1023
        int row = i >> 3, sub = i & 7;   // sub 0-3 hi, 4-7 lo
        int col = (sub & 3) * 8;
        srcA[u] = (sub < 4) ? a_h : a_l;
        srcB[u] = (sub < 4) ? b_h : b_l;
        gOffA[u] = (mBase + row) * K + col;
        gOffB[u] = (nBase + row) * K + col;
        dOff[u] = (uint32_t)row * (LDH * 2) + (uint32_t)sub * 16;
    }

    wmma::fragment<wmma::accumulator, 16, 16, 16, float> acc[2][4];
#pragma unroll
    for (int i = 0; i < 2; i++)
#pragma unroll
        for (int j = 0; j < 4; j++)
            wmma::fill_fragment(acc[i][j], 0.f);

    auto issue = [&](int kk) {
        const int kc = kk << 5;
        const uint32_t sb = sbase + (kk % 3) * STG_B;
#pragma unroll
        for (int u = 0; u < 4; u++) {
            cp16(sb +          dOff[u], srcA[u] + gOffA[u] + kc);
            cp16(sb + TILE_B + dOff[u], srcB[u] + gOffB[u] + kc);
        }
    };

    issue(0); cp_commit();
    issue(1); cp_commit();

    for (int kk = 0; kk < KC; kk++) {
        const int s = kk % 3;
        cp_wait<1>();
        __syncthreads();
        const __half* A2 = (const __half*)(sm + s * STG_B)          + (warpM * 32) * LDH;
        const __half* B2 = (const __half*)(sm + s * STG_B + TILE_B) + (warpN * 64) * LDH;

        wmma::fragment<wmma::matrix_a, 16, 16, 16, __half, wmma::row_major> afh[2], afl[2];
        wmma::fragment<wmma::matrix_b, 16, 16, 16, __half, wmma::col_major> bf[2];
#pragma unroll
        for (int k16 = 0; k16 < 2; k16++) {
            wmma::load_matrix_sync(afh[0], A2 + k16 * 16, LDH);
            wmma::load_matrix_sync(afh[1], A2 + 16 * LDH + k16 * 16, LDH);
            wmma::load_matrix_sync(afl[0], A2 + 32 + k16 * 16, LDH);
            wmma::load_matrix_sync(afl[1], A2 + 16 * LDH + 32 + k16 * 16, LDH);

            // pass 1: hi(A) * hi(B)
            wmma::load_matrix_sync(bf[0], B2 + k16 * 16, LDH);
#pragma unroll
            for (int j = 0; j < 4; j++) {
                if (j < 3)
                    wmma::load_matrix_sync(bf[(j + 1) & 1], B2 + (j + 1) * 16 * LDH + k16 * 16, LDH);
                wmma::mma_sync(acc[0][j], afh[0], bf[j & 1], acc[0][j]);
                wmma::mma_sync(acc[1][j], afh[1], bf[j & 1], acc[1][j]);
            }
            // pass 2: lo(A) * hi(B)
            wmma::load_matrix_sync(bf[0], B2 + k16 * 16, LDH);
#pragma unroll
            for (int j = 0; j < 4; j++) {
                if (j < 3)
                    wmma::load_matrix_sync(bf[(j + 1) & 1], B2 + (j + 1) * 16 * LDH + k16 * 16, LDH);
                wmma::mma_sync(acc[0][j], afl[0], bf[j & 1], acc[0][j]);
                wmma::mma_sync(acc[1][j], afl[1], bf[j & 1], acc[1][j]);
            }
            // pass 3: hi(A) * lo(B)
            wmma::load_matrix_sync(bf[0], B2 + 32 + k16 * 16, LDH);
#pragma unroll
            for (int j = 0; j < 4; j++) {
                if (j < 3)
                    wmma::load_matrix_sync(bf[(j + 1) & 1], B2 + (j + 1) * 16 * LDH + 32 + k16 * 16, LDH);
                wmma::mma_sync(acc[0][j], afh[0], bf[j & 1], acc[0][j]);
                wmma::mma_sync(acc[1][j], afh[1], bf[j & 1], acc[1][j]);
            }
        }
        if (kk + 2 < KC) issue(kk + 2);
        cp_commit();
    }

    cp_wait<0>();
    __syncthreads();
    float* stg = (float*)sm;
#pragma unroll
    for (int i = 0; i < 2; i++)
#pragma unroll
        for (int j = 0; j < 4; j++)
            wmma::store_matrix_sync(stg + (warpM * 32 + i * 16) * LDS_ + warpN * 64 + j * 16,
                                    acc[i][j], LDS_, wmma::mem_row_major);
    __syncthreads();

    if (!FINAL) {
#pragma unroll
        for (int it = 0; it < 32; it++) {
            int i = it * 256 + t;            // half2 index, 8192 total
            int lr = i >> 6, lc = (i & 63) << 1;
            float v0 = fmaxf(stg[lr * LDS_ + lc]     + bias[nBase + lc],     0.f);
            float v1 = fmaxf(stg[lr * LDS_ + lc + 1] + bias[nBase + lc + 1], 0.f);
            __half h0 = __float2half_rn(v0), h1 = __float2half_rn(v1);
            __half l0 = __float2half_rn(v0 - __half2float(h0));
            __half l1 = __float2half_rn(v1 - __half2float(h1));
            size_t o = (size_t)(mBase + lr) * Nout + nBase + lc;
            *(__half2*)(outh + o) = __halves2half2(h0, h1);
            *(__half2*)(outl + o) = __halves2half2(l0, l1);
        }
    } else {
        // fused layer-3 partial dot: each warp handles 16 rows of 128 cols
#pragma unroll
        for (int rr = 0; rr < 16; rr++) {
            int row = warp * 16 + rr;
            float s = 0.f;
#pragma unroll
            for (int q = 0; q < 4; q++) {
                int c = q * 32 + lane;
                float v = fmaxf(stg[row * LDS_ + c] + bias[nBase + c], 0.f);
                s = fmaf(v, s_w3[c], s);
            }
#pragma unroll
            for (int off = 16; off; off >>= 1)
                s += __shfl_down_sync(0xffffffffu, s, off);
            if (lane == 0)
                part[(size_t)blockIdx.x * NPIX + mBase + row] = s;
        }
    }
}

// ---------------- finalize att: sum partials + sigmoid + CAM ----------------
__global__ void finalize_att(const float* __restrict__ b3, const float* __restrict__ cam,
                             float* __restrict__ att_out)
{
    int p = blockIdx.x * 256 + threadIdx.x;
    float s = g_part[0][p] + g_part[1][p] + b3[0];
    float v = 1.f / (1.f + expf(-s));
    float a = (v + cam[p]) * 0.5f;
    g_att[p] = a;
    att_out[p] = a;
}

// ---------------- peak picking ----------------
__global__ void peaks_kernel(float* __restrict__ coords_out)
{
    __shared__ float smv[1024];
    __shared__ float rv[8];
    __shared__ int   ri[8];
    __shared__ int   s_fy, s_fx;

    const int b = blockIdx.x;
    const int t = threadIdx.x;

    for (int i = t; i < 1024; i += 256) smv[i] = g_att[b * 1024 + i];
    __syncthreads();

    for (int k = 0; k < NREG; k++) {
        float best = -1.f;
        int bi = 1 << 30;
        for (int i = t; i < 1024; i += 256) {
            float v = smv[i];
            if (v > best) { best = v; bi = i; }
        }
#pragma unroll
        for (int off = 16; off; off >>= 1) {
            float ov = __shfl_down_sync(0xffffffffu, best, off);
            int   oi = __shfl_down_sync(0xffffffffu, bi, off);
            if (ov > best || (ov == best && oi < bi)) { best = ov; bi = oi; }
        }
        if ((t & 31) == 0) { rv[t >> 5] = best; ri[t >> 5] = bi; }
        __syncthreads();
        if (t == 0) {
            for (int w = 1; w < 8; w++)
                if (rv[w] > best || (rv[w] == best && ri[w] < bi)) { best = rv[w]; bi = ri[w]; }
            int fy = bi >> 5, fx = bi & 31;
            if (!(best > 0.f)) { fy = 16; fx = 16; }
            int y1 = min(max(fy * 16 - (RS / 2), 0), IMG - RS);
            int x1 = min(max(fx * 16 - (RS / 2), 0), IMG - RS);
            int r = b * NREG + k;
            g_xy[r * 2 + 0] = y1;
            g_xy[r * 2 + 1] = x1;
            float* cp = coords_out + r * 4;
            cp[0] = (float)x1;
            cp[1] = (float)y1;
            cp[2] = (float)(x1 + RS);
            cp[3] = (float)(y1 + RS);
            s_fy = fy; s_fx = fx;
        }
        __syncthreads();
        int fy = s_fy, fx = s_fx;
        for (int i = t; i < 1024; i += 256) {
            int y = i >> 5, x = i & 31;
            if (abs(y - fy) <= 5 && abs(x - fx) <= 5) smv[i] = 0.f;
        }
        __syncthreads();
    }
}

// ---------------- region crops ----------------
__global__ void crop_kernel(const float* __restrict__ orig, float* __restrict__ out)
{
    const int r = blockIdx.y;
    const int b = r / NREG;
    const int y1 = g_xy[r * 2 + 0];
    const int x1 = g_xy[r * 2 + 1];

    int idx = blockIdx.x * blockDim.x + threadIdx.x;
    int col4 = idx % 96;
    int tmp  = idx / 96;
    int rrow = tmp % RS;
    int c    = tmp / RS;

    const float* src = orig + (((size_t)(b * 3 + c) * IMG) + (y1 + rrow)) * IMG + x1;
    float4 v = *((const float4*)src + col4);
    float4* dst = (float4*)(out + (size_t)r * (3 * RS * RS)) + idx;
    *dst = v;
}

// ---------------- launch ----------------
extern "C" void kernel_launch(void* const* d_in, const int* in_sizes, int n_in,
                              void* d_out, int out_size)
{
    const float* features = (const float*)d_in[0];
    const float* cam      = (const float*)d_in[1];
    const float* original = (const float*)d_in[2];
    const float* w1 = (const float*)d_in[3];
    const float* b1 = (const float*)d_in[4];
    const float* w2 = (const float*)d_in[5];
    const float* b2 = (const float*)d_in[6];
    const float* w3 = (const float*)d_in[7];
    const float* b3 = (const float*)d_in[8];

    float* out = (float*)d_out;
    const size_t regions_elems = (size_t)B_ * NREG * 3 * RS * RS;
    float* coords_out = out + regions_elems;
    float* att_out    = coords_out + (size_t)B_ * NREG * 4;

    __half *a1h, *a1l, *h1h, *h1l, *w1h, *w1l, *w2h, *w2l;
    float *part;
    cudaGetSymbolAddress((void**)&a1h, g_a1h);
    cudaGetSymbolAddress((void**)&a1l, g_a1l);
    cudaGetSymbolAddress((void**)&h1h, g_h1h);
    cudaGetSymbolAddress((void**)&h1l, g_h1l);
    cudaGetSymbolAddress((void**)&w1h, g_w1h);
    cudaGetSymbolAddress((void**)&w1l, g_w1l);
    cudaGetSymbolAddress((void**)&w2h, g_w2h);
    cudaGetSymbolAddress((void**)&w2l, g_w2l);
    cudaGetSymbolAddress((void**)&part, g_part);

    cudaFuncSetAttribute(gemm_hmma<C1, false>, cudaFuncAttributeMaxDynamicSharedMemorySize, SMEM_DYN);
    cudaFuncSetAttribute(gemm_hmma<N1, true>,  cudaFuncAttributeMaxDynamicSharedMemorySize, SMEM_DYN);

    conv_feat<<<dim3(16, 32, 32), 256>>>(features);
    conv_w<<<(N1 * C1 + 255) / 256, 256>>>(w1, w1h, w1l, N1 * C1);
    conv_w<<<(N2 * N1 + 255) / 256, 256>>>(w2, w2h, w2l, N2 * N1);

    // GEMM1: relu(features x w1^T + b1) -> h1 (fp16 split out)
    gemm_hmma<C1, false><<<dim3(N1 / 128, NPIX / 128), 256, SMEM_DYN>>>(
        a1h, a1l, w1h, w1l, b1, N1, h1h, h1l, nullptr, nullptr);
    // GEMM2 + fused layer3 partial dot
    gemm_hmma<N1, true><<<dim3(N2 / 128, NPIX / 128), 256, SMEM_DYN>>>(
        h1h, h1l, w2h, w2l, b2, N2, nullptr, nullptr, w3, part);

    finalize_att<<<NPIX / 256, 256>>>(b3, cam, att_out);
    peaks_kernel<<<B_, 256>>>(coords_out);
    crop_kernel<<<dim3(432, B_ * NREG), 256>>>(original, out);
}

// round 17
// speedup vs baseline: 1.1480x; 1.0031x over previous
#include <cuda_runtime.h>
#include <cuda_fp16.h>
#include <mma.h>
#include <cstdint>
#include <math.h>

using namespace nvcuda;

#define B_    32
#define C1    1024
#define N1    512
#define N2    256
#define HW    1024
#define NPIX  (B_*HW)
#define IMG   512
#define RS    384
#define NREG  3

// ---------------- static device scratch ----------------
__device__ __align__(16) __half g_a1h[(size_t)NPIX * C1];
__device__ __align__(16) __half g_a1l[(size_t)NPIX * C1];
__device__ __align__(16) __half g_h1h[(size_t)NPIX * N1];
__device__ __align__(16) __half g_h1l[(size_t)NPIX * N1];
__device__ __align__(16) __half g_w1h[N1 * C1];
__device__ __align__(16) __half g_w1l[N1 * C1];
__device__ __align__(16) __half g_w2h[N2 * N1];
__device__ __align__(16) __half g_w2l[N2 * N1];
__device__ float g_part[2][NPIX];
__device__ int   g_xy[B_ * NREG * 2];

// ---------------- PTX helpers ----------------
__device__ __forceinline__ uint32_t smem_u32(const void* p) {
    uint32_t a;
    asm("{ .reg .u64 t; cvta.to.shared.u64 t, %1; cvt.u32.u64 %0, t; }" : "=r"(a) : "l"(p));
    return a;
}
__device__ __forceinline__ void cp16(uint32_t dst, const void* src) {
    asm volatile("cp.async.cg.shared.global [%0], [%1], 16;" :: "r"(dst), "l"(src));
}
__device__ __forceinline__ void cp_commit() { asm volatile("cp.async.commit_group;" ::: "memory"); }
template<int N> __device__ __forceinline__ void cp_wait() { asm volatile("cp.async.wait_group %0;" :: "n"(N) : "memory"); }

// ---------------- prep: features transpose + fp16 split (vectorized writes) ----------
__global__ void conv_feat(const float* __restrict__ f) {
    __shared__ float tile[64][33];
    int b = blockIdx.z, k0 = blockIdx.x * 64, hw0 = blockIdx.y * 32;
    int tx = threadIdx.x & 31, ty = threadIdx.x >> 5;   // 32 x 8
    const float* src = f + ((size_t)b << 20) + (size_t)k0 * 1024 + hw0;
#pragma unroll
    for (int r = 0; r < 8; r++)
        tile[ty + r * 8][tx] = src[(size_t)(ty + r * 8) * 1024 + tx];
    __syncthreads();
#pragma unroll
    for (int r = 0; r < 4; r++) {
        int hw = ty + r * 8;
        float v0 = tile[tx * 2][hw];
        float v1 = tile[tx * 2 + 1][hw];
        __half h0 = __float2half_rn(v0), h1 = __float2half_rn(v1);
        __half l0 = __float2half_rn(v0 - __half2float(h0));
        __half l1 = __float2half_rn(v1 - __half2float(h1));
        size_t o = (((size_t)b << 10) + hw0 + hw) * 1024 + k0 + tx * 2;
        *(__half2*)(g_a1h + o) = __halves2half2(h0, h1);
        *(__half2*)(g_a1l + o) = __halves2half2(l0, l1);
    }
}

__global__ void conv_w(const float* __restrict__ w, __half* __restrict__ oh,
                       __half* __restrict__ ol, int n) {
    int i = blockIdx.x * 256 + threadIdx.x;
    if (i < n) {
        float v = w[i];
        __half h = __float2half_rn(v);
        oh[i] = h;
        ol[i] = __float2half_rn(v - __half2float(h));
    }
}

// ---------------- fused 3-term wmma GEMM: C = relu(A*W^T + b) ----------------
// CTA tile 128x128, 256 threads (8 warps 4x2, warp tile 32x64), BK=32, 3 stages.
// Packed tiles: 128 rows x 72 halves, cols [0:32)=hi, [32:64)=lo, [64:72)=pad.
#define LDH     72
#define TILE_B  (128*LDH*2)         // 18432
#define STG_B   (2*TILE_B)          // 36864 per stage (A2 + B2)
#define LDS_    132
#define SMEM_DYN (3*STG_B)          // 110592

template<int K, bool FINAL>
__global__ __launch_bounds__(256, 2)
void gemm_hmma(const __half* __restrict__ a_h, const __half* __restrict__ a_l,
               const __half* __restrict__ b_h, const __half* __restrict__ b_l,
               const float* __restrict__ bias, int Nout,
               __half* __restrict__ outh, __half* __restrict__ outl,
               const float* __restrict__ w3, float* __restrict__ part)
{
    extern __shared__ char sm[];
    __shared__ float s_w3[128];
    const int t = threadIdx.x;
    const int warp = t >> 5;
    const int lane = t & 31;
    const int warpM = warp >> 1, warpN = warp & 1;   // 4 x 2 warps, each 32 x 64
    const int mBase = blockIdx.y * 128, nBase = blockIdx.x * 128;

    constexpr int KC = K >> 5;       // BK = 32

    const uint32_t sbase = smem_u32(sm);

    if (FINAL && t < 128) s_w3[t] = w3[nBase + t];

    wmma::fragment<wmma::accumulator, 16, 16, 16, float> acc[2][4];
#pragma unroll
    for (int i = 0; i < 2; i++)
#pragma unroll
        for (int j = 0; j < 4; j++)
            wmma::fill_fragment(acc[i][j], 0.f);

    // loader: recompute addresses per call (no long-lived register arrays).
    // i = u*256 + t: row = u*32 + (t>>3), sub = t&7 (0-3 hi, 4-7 lo), col = (sub&3)*8
    auto issue = [&](int kk) {
        const int kc = kk << 5;
        const uint32_t sb = sbase + (kk % 3) * STG_B;
        const int sub = t & 7;
        const int col = (sub & 3) * 8;
        const __half* sA = (sub < 4) ? a_h : a_l;
        const __half* sB = (sub < 4) ? b_h : b_l;
#pragma unroll
        for (int u = 0; u < 4; u++) {
            const int row = u * 32 + (t >> 3);
            const uint32_t d = (uint32_t)row * (LDH * 2) + (uint32_t)sub * 16;
            cp16(sb +          d, sA + (size_t)(mBase + row) * K + kc + col);
            cp16(sb + TILE_B + d, sB + (size_t)(nBase + row) * K + kc + col);
        }
    };

    issue(0); cp_commit();
    issue(1); cp_commit();

    for (int kk = 0; kk < KC; kk++) {
        const int s = kk % 3;
        cp_wait<1>();
        __syncthreads();
        const __half* A2 = (const __half*)(sm + s * STG_B)          + (warpM * 32) * LDH;
        const __half* B2 = (const __half*)(sm + s * STG_B + TILE_B) + (warpN * 64) * LDH;

        wmma::fragment<wmma::matrix_a, 16, 16, 16, __half, wmma::row_major> afh[2], afl[2];
        wmma::fragment<wmma::matrix_b, 16, 16, 16, __half, wmma::col_major> bf;
#pragma unroll
        for (int k16 = 0; k16 < 2; k16++) {
            wmma::load_matrix_sync(afh[0], A2 + k16 * 16, LDH);
            wmma::load_matrix_sync(afh[1], A2 + 16 * LDH + k16 * 16, LDH);
            wmma::load_matrix_sync(afl[0], A2 + 32 + k16 * 16, LDH);
            wmma::load_matrix_sync(afl[1], A2 + 16 * LDH + 32 + k16 * 16, LDH);

            // pass 1: hi(A) * hi(B)
#pragma unroll
            for (int j = 0; j < 4; j++) {
                wmma::load_matrix_sync(bf, B2 + j * 16 * LDH + k16 * 16, LDH);
                wmma::mma_sync(acc[0][j], afh[0], bf, acc[0][j]);
                wmma::mma_sync(acc[1][j], afh[1], bf, acc[1][j]);
            }
            // pass 2: lo(A) * hi(B)
#pragma unroll
            for (int j = 0; j < 4; j++) {
                wmma::load_matrix_sync(bf, B2 + j * 16 * LDH + k16 * 16, LDH);
                wmma::mma_sync(acc[0][j], afl[0], bf, acc[0][j]);
                wmma::mma_sync(acc[1][j], afl[1], bf, acc[1][j]);
            }
            // pass 3: hi(A) * lo(B)
#pragma unroll
            for (int j = 0; j < 4; j++) {
                wmma::load_matrix_sync(bf, B2 + j * 16 * LDH + 32 + k16 * 16, LDH);
                wmma::mma_sync(acc[0][j], afh[0], bf, acc[0][j]);
                wmma::mma_sync(acc[1][j], afh[1], bf, acc[1][j]);
            }
        }
        if (kk + 2 < KC) issue(kk + 2);
        cp_commit();
    }

    cp_wait<0>();
    __syncthreads();
    float* stg = (float*)sm;
#pragma unroll
    for (int i = 0; i < 2; i++)
#pragma unroll
        for (int j = 0; j < 4; j++)
            wmma::store_matrix_sync(stg + (warpM * 32 + i * 16) * LDS_ + warpN * 64 + j * 16,
                                    acc[i][j], LDS_, wmma::mem_row_major);
    __syncthreads();

    if (!FINAL) {
#pragma unroll
        for (int it = 0; it < 32; it++) {
            int i = it * 256 + t;            // half2 index, 8192 total
            int lr = i >> 6, lc = (i & 63) << 1;
            float v0 = fmaxf(stg[lr * LDS_ + lc]     + bias[nBase + lc],     0.f);
            float v1 = fmaxf(stg[lr * LDS_ + lc + 1] + bias[nBase + lc + 1], 0.f);
            __half h0 = __float2half_rn(v0), h1 = __float2half_rn(v1);
            __half l0 = __float2half_rn(v0 - __half2float(h0));
            __half l1 = __float2half_rn(v1 - __half2float(h1));
            size_t o = (size_t)(mBase + lr) * Nout + nBase + lc;
            *(__half2*)(outh + o) = __halves2half2(h0, h1);
            *(__half2*)(outl + o) = __halves2half2(l0, l1);
        }
    } else {
        // fused layer-3 partial dot: each warp handles 16 rows of 128 cols
#pragma unroll
        for (int rr = 0; rr < 16; rr++) {
            int row = warp * 16 + rr;
            float s = 0.f;
#pragma unroll
            for (int q = 0; q < 4; q++) {
                int c = q * 32 + lane;
                float v = fmaxf(stg[row * LDS_ + c] + bias[nBase + c], 0.f);
                s = fmaf(v, s_w3[c], s);
            }
#pragma unroll
            for (int off = 16; off; off >>= 1)
                s += __shfl_down_sync(0xffffffffu, s, off);
            if (lane == 0)
                part[(size_t)blockIdx.x * NPIX + mBase + row] = s;
        }
    }
}

// ---------------- peaks (+ fused att finalize) ----------------
__global__ void peaks_kernel(const float* __restrict__ b3, const float* __restrict__ cam,
                             float* __restrict__ att_out, float* __restrict__ coords_out)
{
    __shared__ float smv[1024];
    __shared__ float rv[8];
    __shared__ int   ri[8];
    __shared__ int   s_fy, s_fx;

    const int b = blockIdx.x;
    const int t = threadIdx.x;
    const float bb = b3[0];

    for (int i = t; i < 1024; i += 256) {
        int p = b * 1024 + i;
        float s = g_part[0][p] + g_part[1][p] + bb;
        float v = 1.f / (1.f + expf(-s));
        float a = (v + cam[p]) * 0.5f;
        smv[i] = a;
        att_out[p] = a;
    }
    __syncthreads();

    for (int k = 0; k < NREG; k++) {
        float best = -1.f;
        int bi = 1 << 30;
        for (int i = t; i < 1024; i += 256) {
            float v = smv[i];
            if (v > best) { best = v; bi = i; }
        }
#pragma unroll
        for (int off = 16; off; off >>= 1) {
            float ov = __shfl_down_sync(0xffffffffu, best, off);
            int   oi = __shfl_down_sync(0xffffffffu, bi, off);
            if (ov > best || (ov == best && oi < bi)) { best = ov; bi = oi; }
        }
        if ((t & 31) == 0) { rv[t >> 5] = best; ri[t >> 5] = bi; }
        __syncthreads();
        if (t == 0) {
            for (int w = 1; w < 8; w++)
                if (rv[w] > best || (rv[w] == best && ri[w] < bi)) { best = rv[w]; bi = ri[w]; }
            int fy = bi >> 5, fx = bi & 31;
            if (!(best > 0.f)) { fy = 16; fx = 16; }
            int y1 = min(max(fy * 16 - (RS / 2), 0), IMG - RS);
            int x1 = min(max(fx * 16 - (RS / 2), 0), IMG - RS);
            int r = b * NREG + k;
            g_xy[r * 2 + 0] = y1;
            g_xy[r * 2 + 1] = x1;
            float* cp = coords_out + r * 4;
            cp[0] = (float)x1;
            cp[1] = (float)y1;
            cp[2] = (float)(x1 + RS);
            cp[3] = (float)(y1 + RS);
            s_fy = fy; s_fx = fx;
        }
        __syncthreads();
        int fy = s_fy, fx = s_fx;
        for (int i = t; i < 1024; i += 256) {
            int y = i >> 5, x = i & 31;
            if (abs(y - fy) <= 5 && abs(x - fx) <= 5) smv[i] = 0.f;
        }
        __syncthreads();
    }
}

// ---------------- region crops ----------------
__global__ void crop_kernel(const float* __restrict__ orig, float* __restrict__ out)
{
    const int r = blockIdx.y;
    const int b = r / NREG;
    const int y1 = g_xy[r * 2 + 0];
    const int x1 = g_xy[r * 2 + 1];

    int idx = blockIdx.x * blockDim.x + threadIdx.x;
    int col4 = idx % 96;
    int tmp  = idx / 96;
    int rrow = tmp % RS;
    int c    = tmp / RS;

    const float* src = orig + (((size_t)(b * 3 + c) * IMG) + (y1 + rrow)) * IMG + x1;
    float4 v = *((const float4*)src + col4);
    float4* dst = (float4*)(out + (size_t)r * (3 * RS * RS)) + idx;
    *dst = v;
}

// ---------------- launch ----------------
extern "C" void kernel_launch(void* const* d_in, const int* in_sizes, int n_in,
                              void* d_out, int out_size)
{
    const float* features = (const float*)d_in[0];
    const float* cam      = (const float*)d_in[1];
    const float* original = (const float*)d_in[2];
    const float* w1 = (const float*)d_in[3];
    const float* b1 = (const float*)d_in[4];
    const float* w2 = (const float*)d_in[5];
    const float* b2 = (const float*)d_in[6];
    const float* w3 = (const float*)d_in[7];
    const float* b3 = (const float*)d_in[8];

    float* out = (float*)d_out;
    const size_t regions_elems = (size_t)B_ * NREG * 3 * RS * RS;
    float* coords_out = out + regions_elems;
    float* att_out    = coords_out + (size_t)B_ * NREG * 4;

    __half *a1h, *a1l, *h1h, *h1l, *w1h, *w1l, *w2h, *w2l;
    float *part;
    cudaGetSymbolAddress((void**)&a1h, g_a1h);
    cudaGetSymbolAddress((void**)&a1l, g_a1l);
    cudaGetSymbolAddress((void**)&h1h, g_h1h);
    cudaGetSymbolAddress((void**)&h1l, g_h1l);
    cudaGetSymbolAddress((void**)&w1h, g_w1h);
    cudaGetSymbolAddress((void**)&w1l, g_w1l);
    cudaGetSymbolAddress((void**)&w2h, g_w2h);
    cudaGetSymbolAddress((void**)&w2l, g_w2l);
    cudaGetSymbolAddress((void**)&part, g_part);

    cudaFuncSetAttribute(gemm_hmma<C1, false>, cudaFuncAttributeMaxDynamicSharedMemorySize, SMEM_DYN);
    cudaFuncSetAttribute(gemm_hmma<N1, true>,  cudaFuncAttributeMaxDynamicSharedMemorySize, SMEM_DYN);

    conv_feat<<<dim3(16, 32, 32), 256>>>(features);
    conv_w<<<(N1 * C1 + 255) / 256, 256>>>(w1, w1h, w1l, N1 * C1);
    conv_w<<<(N2 * N1 + 255) / 256, 256>>>(w2, w2h, w2l, N2 * N1);

    // GEMM1: relu(features x w1^T + b1) -> h1 (fp16 split out)
    gemm_hmma<C1, false><<<dim3(N1 / 128, NPIX / 128), 256, SMEM_DYN>>>(
        a1h, a1l, w1h, w1l, b1, N1, h1h, h1l, nullptr, nullptr);
    // GEMM2 + fused layer3 partial dot
    gemm_hmma<N1, true><<<dim3(N2 / 128, NPIX / 128), 256, SMEM_DYN>>>(
        h1h, h1l, w2h, w2l, b2, N2, nullptr, nullptr, w3, part);

    // peaks (+att finalize) + coords
    peaks_kernel<<<B_, 256>>>(b3, cam, att_out, coords_out);
    crop_kernel<<<dim3(432, B_ * NREG), 256>>>(original, out);
}